// round 15
// baseline (speedup 1.0000x reference)
#include <cuda_runtime.h>
#include <cstdint>
#include <cmath>

#define GH 512
#define GK 50
#define KPAD 52
#define GT 1024
#define GB 128
#define GM (GB * GT)
#define BPP 52

// Scratch for projected features [B*T, K]
__device__ float g_feats[(size_t)GM * GK + 64];

// Packed fp32x2 FMA (sm_103a): acc = x * w + acc
#define FFMA2(acc, x, w) \
    asm("fma.rn.f32x2 %0, %1, %2, %0;" : "+l"(acc) : "l"(x), "l"(w))

// ---------------------------------------------------------------------------
// Kernel 1 (proven, 212-213us): feats = hidden @ W^T + b
// 256 CTAs x 256 threads, 2 rows/thread. W transposed in smem [h][52],
// broadcast LDS.128 conflict-free; all math packed f32x2 FFMA.
// ---------------------------------------------------------------------------
__global__ __launch_bounds__(256, 1) void gemm_kernel(
    const float* __restrict__ hidden, const float* __restrict__ W,
    const float* __restrict__ bias) {
    extern __shared__ float Wt[];  // [GH][KPAD]
    const int tid = threadIdx.x;

    for (int idx = tid; idx < GK * GH; idx += 256) {
        int k = idx >> 9;
        int h = idx & 511;
        Wt[h * KPAD + k] = W[idx];
    }
    __syncthreads();

    const size_t base = (size_t)blockIdx.x * 512;
    const float4* r0 = reinterpret_cast<const float4*>(hidden + (base + tid) * GH);
    const float4* r1 = reinterpret_cast<const float4*>(hidden + (base + tid + 256) * GH);

    unsigned long long acc0[25], acc1[25];
#pragma unroll
    for (int q = 0; q < 25; q++) { acc0[q] = 0ull; acc1[q] = 0ull; }

    float4 a0 = r0[0], a1 = r0[1];
    float4 b0 = r1[0], b1 = r1[1];

    for (int hc = 0; hc < 64; hc++) {
        float xs0[8] = {a0.x, a0.y, a0.z, a0.w, a1.x, a1.y, a1.z, a1.w};
        float xs1[8] = {b0.x, b0.y, b0.z, b0.w, b1.x, b1.y, b1.z, b1.w};
        if (hc < 63) {
            a0 = r0[2 * hc + 2]; a1 = r0[2 * hc + 3];
            b0 = r1[2 * hc + 2]; b1 = r1[2 * hc + 3];
        }
#pragma unroll
        for (int u = 0; u < 8; u++) {
            const int h = hc * 8 + u;
            unsigned long long X0, X1;
            asm("mov.b64 %0, {%1, %1};" : "=l"(X0) : "r"(__float_as_uint(xs0[u])));
            asm("mov.b64 %0, {%1, %1};" : "=l"(X1) : "r"(__float_as_uint(xs1[u])));
            const float* wr = Wt + h * KPAD;
#pragma unroll
            for (int q = 0; q < 12; q++) {
                ulonglong2 w = *reinterpret_cast<const ulonglong2*>(wr + q * 4);
                FFMA2(acc0[2 * q],     X0, w.x);
                FFMA2(acc0[2 * q + 1], X0, w.y);
                FFMA2(acc1[2 * q],     X1, w.x);
                FFMA2(acc1[2 * q + 1], X1, w.y);
            }
            unsigned long long wl = *reinterpret_cast<const unsigned long long*>(wr + 48);
            FFMA2(acc0[24], X0, wl);
            FFMA2(acc1[24], X1, wl);
        }
    }

    float2* o0 = reinterpret_cast<float2*>(g_feats + (base + tid) * GK);
    float2* o1 = reinterpret_cast<float2*>(g_feats + (base + tid + 256) * GK);
    const float2* bb = reinterpret_cast<const float2*>(bias);
#pragma unroll
    for (int q = 0; q < 25; q++) {
        float2 bv = bb[q];
        float2 v0 = *reinterpret_cast<float2*>(&acc0[q]);
        float2 v1 = *reinterpret_cast<float2*>(&acc1[q]);
        v0.x += bv.x; v0.y += bv.y;
        v1.x += bv.x; v1.y += bv.y;
        o0[q] = v0;
        o1[q] = v1;
    }
}

// ---------------------------------------------------------------------------
// Pairwise argmax tree (select-form). Adjacent pairs keep index-ordered
// subranges; strict '>' == jnp.argmax first-max tie-breaking.
// ---------------------------------------------------------------------------
template <int Wd>
__device__ __forceinline__ void argmax_tree(float* val, int* id) {
    if constexpr (Wd > 1) {
        constexpr int P = Wd >> 1;
#pragma unroll
        for (int m = 0; m < P; m++) {
            bool g = val[2 * m + 1] > val[2 * m];
            val[m] = g ? val[2 * m + 1] : val[2 * m];
            id[m]  = g ? id[2 * m + 1]  : id[2 * m];
        }
        if constexpr (Wd & 1) { val[P] = val[Wd - 1]; id[P] = id[Wd - 1]; }
        argmax_tree<((Wd + 1) >> 1)>(val, id);
    }
}

// One batch's DP step body: returns (best, bi) for state j from slice i0.
__device__ __forceinline__ void dp_step(const float* vr, const float* tr,
                                        int i0, float& best, int& bi) {
    float cand[13];
    int id[13];
#pragma unroll
    for (int ii = 0; ii < 13; ii++) {
        cand[ii] = vr[i0 + ii] + tr[ii];
        id[ii] = i0 + ii;
    }
    argmax_tree<13>(cand, id);
    best = cand[0];
    bi = id[0];

    float ov = __shfl_xor_sync(0xffffffffu, best, 1);
    int   oi = __shfl_xor_sync(0xffffffffu, bi, 1);
    bool g1 = (ov > best) || (ov == best && oi < bi);
    best = g1 ? ov : best;
    bi   = g1 ? oi : bi;
    ov = __shfl_xor_sync(0xffffffffu, best, 2);
    oi = __shfl_xor_sync(0xffffffffu, bi, 2);
    bool g2 = (ov > best) || (ov == best && oi < bi);
    best = g2 ? ov : best;
    bi   = g2 ? oi : bi;
}

// ---------------------------------------------------------------------------
// Kernel 2: batch-PAIR Viterbi. 64 CTAs, each runs TWO independent DP chains
// (batches 2*cta, 2*cta+1) in the same 224 threads / 7 warps. The two
// chains' latency stalls interleave in the scheduler; tr[13] registers are
// shared (same transition matrix); ONE barrier per step covers both.
// Backtraces run in parallel in two different warps.
// ---------------------------------------------------------------------------
// smem byte offsets (viterbi)
#define VS_BP0   0               // 1023*52 = 53196 -> pad 53248
#define VS_BP1   53248
#define VS_VB0   106496          // [2][64] floats = 512
#define VS_VB1   107008
#define VS_RED0  107520          // 64 floats
#define VS_RED1  107776
#define VS_TAG0  108032          // 1024 B
#define VS_TAG1  109056
#define VS_TOTAL 110080

__global__ __launch_bounds__(224, 1) void viterbi_kernel(
    const float* __restrict__ trans, const float* __restrict__ startt,
    const float* __restrict__ stopt, float* __restrict__ out) {
    extern __shared__ char smv[];
    unsigned char* bp0 = reinterpret_cast<unsigned char*>(smv + VS_BP0);
    unsigned char* bp1 = reinterpret_cast<unsigned char*>(smv + VS_BP1);
    float* vb0 = reinterpret_cast<float*>(smv + VS_VB0);
    float* vb1 = reinterpret_cast<float*>(smv + VS_VB1);
    float* red0 = reinterpret_cast<float*>(smv + VS_RED0);
    float* red1 = reinterpret_cast<float*>(smv + VS_RED1);
    unsigned char* tg0 = reinterpret_cast<unsigned char*>(smv + VS_TAG0);
    unsigned char* tg1 = reinterpret_cast<unsigned char*>(smv + VS_TAG1);

    const int b0 = blockIdx.x * 2;
    const int b1 = b0 + 1;
    const int tid = threadIdx.x;
    const int j = tid >> 2;
    const int r = tid & 3;
    const int i0 = r * 13;
    const float* F0 = g_feats + (size_t)b0 * GT * GK;
    const float* F1 = g_feats + (size_t)b1 * GT * GK;
    const bool act = (j < GK);

    // Shared transition slice (identical for both batches)
    float tr[13];
#pragma unroll
    for (int ii = 0; ii < 13; ii++) {
        int i = i0 + ii;
        tr[ii] = (act && i < GK) ? trans[i * GK + j] : -INFINITY;
    }

    // Pads + t=0 init for both chains
    if (tid >= GK && tid < 64) {
        vb0[tid] = -INFINITY; vb0[64 + tid] = -INFINITY;
        vb1[tid] = -INFINITY; vb1[64 + tid] = -INFINITY;
    }
    if (r == 0 && act) {
        float st = startt[j];
        vb0[j] = F0[j] + st;
        vb1[j] = F1[j] + st;
    }

    // Feats prefetch rings, depth 4, both batches
    float fr0[4], fr1[4];
    if (r == 0 && act) {
#pragma unroll
        for (int u = 0; u < 4; u++) {
            fr0[u] = F0[(1 + u) * GK + j];
            fr1[u] = F1[(1 + u) * GK + j];
        }
    }
    __syncthreads();

    for (int t = 1; t < GT; t += 4) {
#pragma unroll
        for (int u = 0; u < 4; u++) {
            const int tt = t + u;
            if (tt < GT) {  // uniform across block
                const int roff = ((tt - 1) & 1) << 6;
                const int woff = (tt & 1) << 6;
                float best0, best1;
                int bi0, bi1;
                dp_step(vb0 + roff, tr, i0, best0, bi0);
                dp_step(vb1 + roff, tr, i0, best1, bi1);

                if (r == 0 && act) {
                    vb0[woff + j] = fr0[u] + best0;
                    vb1[woff + j] = fr1[u] + best1;
                    bp0[(tt - 1) * BPP + j] = (unsigned char)bi0;
                    bp1[(tt - 1) * BPP + j] = (unsigned char)bi1;
                    int tn = tt + 4;
                    if (tn > GT - 1) tn = GT - 1;
                    fr0[u] = F0[tn * GK + j];
                    fr1[u] = F1[tn * GK + j];
                }
                __syncthreads();
            }
        }
    }

    // Final: v at t=1023 lives in buffer half 1
    if (r == 0 && act) {
        float sp = stopt[j];
        red0[j] = vb0[64 + j] + sp;
        red1[j] = vb1[64 + j] + sp;
    }
    __syncthreads();

    // Two parallel backtraces in different warps
    if (tid == 0 || tid == 32) {
        float* red = (tid == 0) ? red0 : red1;
        unsigned char* bp = (tid == 0) ? bp0 : bp1;
        unsigned char* tg = (tid == 0) ? tg0 : tg1;
        const int b = (tid == 0) ? b0 : b1;
        float best = -INFINITY;
        int bj = 0;
        for (int k = 0; k < GK; k++) {
            float s = red[k];
            if (s > best) { best = s; bj = k; }
        }
        out[b] = best;
        int tag = bj;
        tg[GT - 1] = (unsigned char)tag;
        for (int k = GT - 2; k >= 0; k--) {
            tag = bp[k * BPP + tag];
            tg[k] = (unsigned char)tag;
        }
    }
    __syncthreads();

    // Parallel coalesced tag writeout, both batches
    float* tout0 = out + GB + (size_t)b0 * GT;
    float* tout1 = out + GB + (size_t)b1 * GT;
    for (int k = tid; k < GT; k += 224) {
        tout0[k] = (float)tg0[k];
        tout1[k] = (float)tg1[k];
    }
}

extern "C" void kernel_launch(void* const* d_in, const int* in_sizes, int n_in,
                              void* d_out, int out_size) {
    const float* hidden = (const float*)d_in[0];
    const float* W      = (const float*)d_in[1];
    const float* bias   = (const float*)d_in[2];
    const float* trans  = (const float*)d_in[3];
    const float* startt = (const float*)d_in[4];
    const float* stopt  = (const float*)d_in[5];
    float* out = (float*)d_out;

    const size_t wsm = (size_t)GH * KPAD * sizeof(float);          // 106,496 B
    cudaFuncSetAttribute(gemm_kernel, cudaFuncAttributeMaxDynamicSharedMemorySize, (int)wsm);
    gemm_kernel<<<GM / 512, 256, wsm>>>(hidden, W, bias);

    cudaFuncSetAttribute(viterbi_kernel, cudaFuncAttributeMaxDynamicSharedMemorySize, VS_TOTAL);
    viterbi_kernel<<<GB / 2, 224, VS_TOTAL>>>(trans, startt, stopt, out);
}

// round 16
// speedup vs baseline: 1.3118x; 1.3118x over previous
#include <cuda_runtime.h>
#include <cstdint>
#include <cmath>

#define GH 512
#define GK 50
#define KPAD 52
#define GT 1024
#define GB 128
#define GM (GB * GT)
#define BPP 52
#define RPC 886            // rows per persistent gemm CTA (148*886 >= 131072)

// Scratch for projected features [B*T, K]
__device__ float g_feats[(size_t)GM * GK + 64];

// Packed fp32x2 FMA (sm_103a): acc = x * w + acc
#define FFMA2(acc, x, w) \
    asm("fma.rn.f32x2 %0, %1, %2, %0;" : "+l"(acc) : "l"(x), "l"(w))

// ---------------------------------------------------------------------------
// Kernel 1: persistent GEMM, grid = 148 (one CTA per SM; 3.46 row-units per
// thread instead of the 2-wave version's 4). Inner loop byte-identical to
// the proven 212us kernel (serial k, f32x2 FFMA, Wt broadcast LDS) so
// per-row summation order is unchanged -> rel_err stays 0.
// ---------------------------------------------------------------------------
__global__ __launch_bounds__(256, 1) void gemm_kernel(
    const float* __restrict__ hidden, const float* __restrict__ W,
    const float* __restrict__ bias) {
    extern __shared__ float Wt[];  // [GH][KPAD]
    const int tid = threadIdx.x;

    for (int idx = tid; idx < GK * GH; idx += 256) {
        int k = idx >> 9;
        int h = idx & 511;
        Wt[h * KPAD + k] = W[idx];
    }
    __syncthreads();

    const int start = blockIdx.x * RPC;
    const int end   = (start + RPC < GM) ? (start + RPC) : GM;

    for (int row0 = start; row0 < end; row0 += 256) {
        const int row = row0 + tid;
        if (row < end) {
            const float4* hx = reinterpret_cast<const float4*>(
                hidden + (size_t)row * GH);

            unsigned long long acc[25];
#pragma unroll
            for (int q = 0; q < 25; q++) acc[q] = 0ull;

            float4 a0 = hx[0], a1 = hx[1];
            for (int hc = 0; hc < 64; hc++) {
                float xs[8] = {a0.x, a0.y, a0.z, a0.w, a1.x, a1.y, a1.z, a1.w};
                if (hc < 63) { a0 = hx[2 * hc + 2]; a1 = hx[2 * hc + 3]; }
#pragma unroll
                for (int u = 0; u < 8; u++) {
                    const int h = hc * 8 + u;
                    unsigned long long X;
                    asm("mov.b64 %0, {%1, %1};" : "=l"(X) : "r"(__float_as_uint(xs[u])));
                    const float* wr = Wt + h * KPAD;
#pragma unroll
                    for (int q = 0; q < 12; q++) {
                        ulonglong2 w = *reinterpret_cast<const ulonglong2*>(wr + q * 4);
                        FFMA2(acc[2 * q],     X, w.x);
                        FFMA2(acc[2 * q + 1], X, w.y);
                    }
                    unsigned long long wl =
                        *reinterpret_cast<const unsigned long long*>(wr + 48);
                    FFMA2(acc[24], X, wl);
                }
            }

            float2* o = reinterpret_cast<float2*>(g_feats + (size_t)row * GK);
            const float2* bb = reinterpret_cast<const float2*>(bias);
#pragma unroll
            for (int q = 0; q < 25; q++) {
                float2 bv = bb[q];
                float2 v = *reinterpret_cast<float2*>(&acc[q]);
                v.x += bv.x; v.y += bv.y;
                o[q] = v;
            }
        }
    }
}

// ---------------------------------------------------------------------------
// Pairwise argmax tree (select-form). Adjacent pairs keep index-ordered
// subranges; strict '>' (right wins only if strictly greater) implements
// jnp.argmax first-max tie-breaking exactly.
// ---------------------------------------------------------------------------
template <int Wd>
__device__ __forceinline__ void argmax_tree(float* val, int* id) {
    if constexpr (Wd > 1) {
        constexpr int P = Wd >> 1;
#pragma unroll
        for (int m = 0; m < P; m++) {
            bool g = val[2 * m + 1] > val[2 * m];
            val[m] = g ? val[2 * m + 1] : val[2 * m];
            id[m]  = g ? id[2 * m + 1]  : id[2 * m];
        }
        if constexpr (Wd & 1) { val[P] = val[Wd - 1]; id[P] = id[Wd - 1]; }
        argmax_tree<((Wd + 1) >> 1)>(val, id);
    }
}

// ---------------------------------------------------------------------------
// Kernel 2 (round-3/round-13 certified, 308-311us): fused Viterbi forward +
// backtrace. One CTA (224 thr / 7 warps) per batch. Thread (j, r):
// j = tid>>2, r = tid&3, 13-wide scalar i-slices (conflict-free LDS).
// Tree argmax (depth 4) + two shfl merges. Backpointers entirely in smem ->
// backtrace is an LDS pointer chase. Parallel coalesced tag writeout.
// ---------------------------------------------------------------------------
__global__ __launch_bounds__(224, 1) void viterbi_kernel(
    const float* __restrict__ trans, const float* __restrict__ startt,
    const float* __restrict__ stopt, float* __restrict__ out) {
    extern __shared__ char smv[];
    unsigned char* bp = reinterpret_cast<unsigned char*>(smv);        // 1023*52
    float* vbuf = reinterpret_cast<float*>(smv + 53200);              // [2][64]
    float* red  = vbuf + 128;                                         // [64]
    unsigned char* tags = reinterpret_cast<unsigned char*>(red + 64); // [1024]

    const int b = blockIdx.x;
    const int tid = threadIdx.x;
    const int j = tid >> 2;
    const int r = tid & 3;
    const float* F = g_feats + (size_t)b * GT * GK;

    const int i0 = r * 13;

    float tr[13];
#pragma unroll
    for (int ii = 0; ii < 13; ii++) {
        int i = i0 + ii;
        tr[ii] = (j < GK && i < GK) ? trans[i * GK + j] : -INFINITY;
    }

    if (tid >= GK && tid < 64) { vbuf[tid] = -INFINITY; vbuf[64 + tid] = -INFINITY; }
    if (r == 0 && j < GK) vbuf[j] = F[j] + startt[j];

    float fr[4];
    if (r == 0 && j < GK) {
#pragma unroll
        for (int u = 0; u < 4; u++) fr[u] = F[(1 + u) * GK + j];
    }
    __syncthreads();

    for (int t = 1; t < GT; t += 4) {
#pragma unroll
        for (int u = 0; u < 4; u++) {
            const int tt = t + u;
            if (tt < GT) {  // uniform across block
                const float* vr = vbuf + (((tt - 1) & 1) << 6);
                float cand[13];
                int id[13];
#pragma unroll
                for (int ii = 0; ii < 13; ii++) {
                    cand[ii] = vr[i0 + ii] + tr[ii];
                    id[ii] = i0 + ii;
                }
                argmax_tree<13>(cand, id);
                float best = cand[0];
                int bi = id[0];

                float ov = __shfl_xor_sync(0xffffffffu, best, 1);
                int   oi = __shfl_xor_sync(0xffffffffu, bi, 1);
                bool g1 = (ov > best) || (ov == best && oi < bi);
                best = g1 ? ov : best;
                bi   = g1 ? oi : bi;
                ov = __shfl_xor_sync(0xffffffffu, best, 2);
                oi = __shfl_xor_sync(0xffffffffu, bi, 2);
                bool g2 = (ov > best) || (ov == best && oi < bi);
                best = g2 ? ov : best;
                bi   = g2 ? oi : bi;

                if (r == 0 && j < GK) {
                    float* vw = vbuf + ((tt & 1) << 6);
                    vw[j] = fr[u] + best;
                    bp[(tt - 1) * BPP + j] = (unsigned char)bi;
                    int tn = tt + 4;
                    if (tn > GT - 1) tn = GT - 1;
                    fr[u] = F[tn * GK + j];
                }
                __syncthreads();
            }
        }
    }

    if (r == 0 && j < GK) red[j] = vbuf[64 + j] + stopt[j];
    __syncthreads();

    if (tid == 0) {
        float best = -INFINITY;
        int bj = 0;
        for (int k = 0; k < GK; k++) {
            float s = red[k];
            if (s > best) { best = s; bj = k; }
        }
        out[b] = best;
        int tag = bj;
        tags[GT - 1] = (unsigned char)tag;
        for (int k = GT - 2; k >= 0; k--) {
            tag = bp[k * BPP + tag];
            tags[k] = (unsigned char)tag;
        }
    }
    __syncthreads();

    float* tout = out + GB + (size_t)b * GT;
    for (int k = tid; k < GT; k += 224) tout[k] = (float)tags[k];
}

extern "C" void kernel_launch(void* const* d_in, const int* in_sizes, int n_in,
                              void* d_out, int out_size) {
    const float* hidden = (const float*)d_in[0];
    const float* W      = (const float*)d_in[1];
    const float* bias   = (const float*)d_in[2];
    const float* trans  = (const float*)d_in[3];
    const float* startt = (const float*)d_in[4];
    const float* stopt  = (const float*)d_in[5];
    float* out = (float*)d_out;

    const size_t wsm = (size_t)GH * KPAD * sizeof(float);          // 106,496 B
    cudaFuncSetAttribute(gemm_kernel, cudaFuncAttributeMaxDynamicSharedMemorySize, (int)wsm);
    gemm_kernel<<<148, 256, wsm>>>(hidden, W, bias);

    const size_t vsm = 53200 + (128 + 64) * sizeof(float) + 1024;  // 54,992 B
    cudaFuncSetAttribute(viterbi_kernel, cudaFuncAttributeMaxDynamicSharedMemorySize, (int)vsm);
    viterbi_kernel<<<GB, 224, vsm>>>(trans, startt, stopt, out);
}

// round 17
// speedup vs baseline: 1.4177x; 1.0807x over previous
#include <cuda_runtime.h>
#include <cstdint>
#include <cmath>

#define GH 512
#define GK 50
#define KPAD 52
#define GT 1024
#define GB 128
#define GM (GB * GT)
#define BPP 52

// Scratch for projected features [B*T, K]
__device__ float g_feats[(size_t)GM * GK + 64];

// Packed fp32x2 ops (sm_103a)
#define FFMA2(acc, x, w) \
    asm("fma.rn.f32x2 %0, %1, %2, %0;" : "+l"(acc) : "l"(x), "l"(w))
#define FADD2(res, a, b) \
    asm("add.rn.f32x2 %0, %1, %2;" : "=l"(res) : "l"(a), "l"(b))

// ---------------------------------------------------------------------------
// Kernel 1 (certified 212-213us, measured 3x): feats = hidden @ W^T + b
// 256 CTAs x 256 threads (2 CTAs/SM -> one balanced wave), 2 rows/thread.
// W transposed in smem [h][52], broadcast LDS.128 conflict-free; all math
// packed f32x2 FFMA; software-pipelined row loads.
// ---------------------------------------------------------------------------
__global__ __launch_bounds__(256, 1) void gemm_kernel(
    const float* __restrict__ hidden, const float* __restrict__ W,
    const float* __restrict__ bias) {
    extern __shared__ float Wt[];  // [GH][KPAD]
    const int tid = threadIdx.x;

    for (int idx = tid; idx < GK * GH; idx += 256) {
        int k = idx >> 9;
        int h = idx & 511;
        Wt[h * KPAD + k] = W[idx];
    }
    __syncthreads();

    const size_t base = (size_t)blockIdx.x * 512;
    const float4* r0 = reinterpret_cast<const float4*>(hidden + (base + tid) * GH);
    const float4* r1 = reinterpret_cast<const float4*>(hidden + (base + tid + 256) * GH);

    unsigned long long acc0[25], acc1[25];
#pragma unroll
    for (int q = 0; q < 25; q++) { acc0[q] = 0ull; acc1[q] = 0ull; }

    float4 a0 = r0[0], a1 = r0[1];
    float4 b0 = r1[0], b1 = r1[1];

    for (int hc = 0; hc < 64; hc++) {
        float xs0[8] = {a0.x, a0.y, a0.z, a0.w, a1.x, a1.y, a1.z, a1.w};
        float xs1[8] = {b0.x, b0.y, b0.z, b0.w, b1.x, b1.y, b1.z, b1.w};
        if (hc < 63) {
            a0 = r0[2 * hc + 2]; a1 = r0[2 * hc + 3];
            b0 = r1[2 * hc + 2]; b1 = r1[2 * hc + 3];
        }
#pragma unroll
        for (int u = 0; u < 8; u++) {
            const int h = hc * 8 + u;
            unsigned long long X0, X1;
            asm("mov.b64 %0, {%1, %1};" : "=l"(X0) : "r"(__float_as_uint(xs0[u])));
            asm("mov.b64 %0, {%1, %1};" : "=l"(X1) : "r"(__float_as_uint(xs1[u])));
            const float* wr = Wt + h * KPAD;
#pragma unroll
            for (int q = 0; q < 12; q++) {
                ulonglong2 w = *reinterpret_cast<const ulonglong2*>(wr + q * 4);
                FFMA2(acc0[2 * q],     X0, w.x);
                FFMA2(acc0[2 * q + 1], X0, w.y);
                FFMA2(acc1[2 * q],     X1, w.x);
                FFMA2(acc1[2 * q + 1], X1, w.y);
            }
            unsigned long long wl = *reinterpret_cast<const unsigned long long*>(wr + 48);
            FFMA2(acc0[24], X0, wl);
            FFMA2(acc1[24], X1, wl);
        }
    }

    float2* o0 = reinterpret_cast<float2*>(g_feats + (base + tid) * GK);
    float2* o1 = reinterpret_cast<float2*>(g_feats + (base + tid + 256) * GK);
    const float2* bb = reinterpret_cast<const float2*>(bias);
#pragma unroll
    for (int q = 0; q < 25; q++) {
        float2 bv = bb[q];
        float2 v0 = *reinterpret_cast<float2*>(&acc0[q]);
        float2 v1 = *reinterpret_cast<float2*>(&acc1[q]);
        v0.x += bv.x; v0.y += bv.y;
        v1.x += bv.x; v1.y += bv.y;
        o0[q] = v0;
        o1[q] = v1;
    }
}

// ---------------------------------------------------------------------------
// Pairwise argmax tree (select-form, compile-time ids). Adjacent pairs keep
// index-ordered subranges; strict '>' == jnp.argmax first-max tie-breaking.
// ---------------------------------------------------------------------------
template <int Wd>
__device__ __forceinline__ void argmax_tree(float* val, int* id) {
    if constexpr (Wd > 1) {
        constexpr int P = Wd >> 1;
#pragma unroll
        for (int m = 0; m < P; m++) {
            bool g = val[2 * m + 1] > val[2 * m];
            val[m] = g ? val[2 * m + 1] : val[2 * m];
            id[m]  = g ? id[2 * m + 1]  : id[2 * m];
        }
        if constexpr (Wd & 1) { val[P] = val[Wd - 1]; id[P] = id[Wd - 1]; }
        argmax_tree<((Wd + 1) >> 1)>(val, id);
    }
}

// ---------------------------------------------------------------------------
// Kernel 2: Viterbi, 224 threads / 7 warps (certified topology). ONE change
// vs the certified 307us kernel: candidate stage uses 14-wide slices at
// i0 = 14r (even -> aligned LDS.64, banks {0,1}{14,15}{28,29}{10,11}
// conflict-free) with 7 packed FADD2 and compile-time tree ids, cutting
// per-thread inst ~91 -> ~68 (issue-rate bound at ~1.1 inst/cyc/SM).
// Everything else byte-identical.
// ---------------------------------------------------------------------------
__global__ __launch_bounds__(224, 1) void viterbi_kernel(
    const float* __restrict__ trans, const float* __restrict__ startt,
    const float* __restrict__ stopt, float* __restrict__ out) {
    extern __shared__ char smv[];
    unsigned char* bp = reinterpret_cast<unsigned char*>(smv);        // 1023*52
    float* vbuf = reinterpret_cast<float*>(smv + 53200);              // [2][64]
    float* red  = vbuf + 128;                                         // [64]
    unsigned char* tags = reinterpret_cast<unsigned char*>(red + 64); // [1024]

    const int b = blockIdx.x;
    const int tid = threadIdx.x;
    const int j = tid >> 2;        // 0..55 (j >= 50 pad)
    const int r = tid & 3;
    const int i0 = r * 14;         // 0,14,28,42
    const float* F = g_feats + (size_t)b * GT * GK;
    const bool act = (j < GK);

    // Packed transition slice: trp[p] = (tr[i0+2p], tr[i0+2p+1]), -inf pads
    unsigned long long trp[7];
#pragma unroll
    for (int p = 0; p < 7; p++) {
        int ia = i0 + 2 * p, ib = ia + 1;
        float ta = (act && ia < GK) ? trans[ia * GK + j] : -INFINITY;
        float tb = (act && ib < GK) ? trans[ib * GK + j] : -INFINITY;
        asm("mov.b64 %0, {%1, %2};" : "=l"(trp[p])
            : "r"(__float_as_uint(ta)), "r"(__float_as_uint(tb)));
    }

    // Pads: slots [50,64) of both vbuf halves to -inf
    if (tid >= GK && tid < 64) { vbuf[tid] = -INFINITY; vbuf[64 + tid] = -INFINITY; }
    if (r == 0 && act) vbuf[j] = F[j] + startt[j];

    // Feats prefetch ring, depth 4
    float fr[4];
    if (r == 0 && act) {
#pragma unroll
        for (int u = 0; u < 4; u++) fr[u] = F[(1 + u) * GK + j];
    }
    __syncthreads();

    for (int t = 1; t < GT; t += 4) {
#pragma unroll
        for (int u = 0; u < 4; u++) {
            const int tt = t + u;
            if (tt < GT) {  // uniform across block: barrier inside is legal
                const float* vr = vbuf + (((tt - 1) & 1) << 6) + i0;
                float cand[14];
                int id[14];
#pragma unroll
                for (int p = 0; p < 7; p++) {
                    unsigned long long x =
                        *reinterpret_cast<const unsigned long long*>(vr + 2 * p);
                    unsigned long long res;
                    FADD2(res, x, trp[p]);
                    float2 rf = *reinterpret_cast<float2*>(&res);
                    cand[2 * p]     = rf.x;
                    cand[2 * p + 1] = rf.y;
                    id[2 * p]     = 2 * p;       // compile-time constants
                    id[2 * p + 1] = 2 * p + 1;
                }
                argmax_tree<14>(cand, id);
                float best = cand[0];
                int bi = i0 + id[0];

                // Merge 4 partials across r (lower global index wins ties)
                float ov = __shfl_xor_sync(0xffffffffu, best, 1);
                int   oi = __shfl_xor_sync(0xffffffffu, bi, 1);
                bool g1 = (ov > best) || (ov == best && oi < bi);
                best = g1 ? ov : best;
                bi   = g1 ? oi : bi;
                ov = __shfl_xor_sync(0xffffffffu, best, 2);
                oi = __shfl_xor_sync(0xffffffffu, bi, 2);
                bool g2 = (ov > best) || (ov == best && oi < bi);
                best = g2 ? ov : best;
                bi   = g2 ? oi : bi;

                if (r == 0 && act) {
                    vbuf[((tt & 1) << 6) + j] = fr[u] + best;
                    bp[(tt - 1) * BPP + j] = (unsigned char)bi;
                    int tn = tt + 4;
                    if (tn > GT - 1) tn = GT - 1;
                    fr[u] = F[tn * GK + j];
                }
                __syncthreads();
            }
        }
    }

    // Final: v at t=1023 lives in buffer half 1
    if (r == 0 && act) red[j] = vbuf[64 + j] + stopt[j];
    __syncthreads();

    if (tid == 0) {
        float best = -INFINITY;
        int bj = 0;
        for (int k = 0; k < GK; k++) {
            float s = red[k];
            if (s > best) { best = s; bj = k; }
        }
        out[b] = best;
        int tag = bj;
        tags[GT - 1] = (unsigned char)tag;
        for (int k = GT - 2; k >= 0; k--) {
            tag = bp[k * BPP + tag];
            tags[k] = (unsigned char)tag;
        }
    }
    __syncthreads();

    // Parallel coalesced tag writeout
    float* tout = out + GB + (size_t)b * GT;
    for (int k = tid; k < GT; k += 224) tout[k] = (float)tags[k];
}

extern "C" void kernel_launch(void* const* d_in, const int* in_sizes, int n_in,
                              void* d_out, int out_size) {
    const float* hidden = (const float*)d_in[0];
    const float* W      = (const float*)d_in[1];
    const float* bias   = (const float*)d_in[2];
    const float* trans  = (const float*)d_in[3];
    const float* startt = (const float*)d_in[4];
    const float* stopt  = (const float*)d_in[5];
    float* out = (float*)d_out;

    const size_t wsm = (size_t)GH * KPAD * sizeof(float);          // 106,496 B
    cudaFuncSetAttribute(gemm_kernel, cudaFuncAttributeMaxDynamicSharedMemorySize, (int)wsm);
    gemm_kernel<<<GM / 512, 256, wsm>>>(hidden, W, bias);

    const size_t vsm = 53200 + (128 + 64) * sizeof(float) + 1024;  // 54,992 B
    cudaFuncSetAttribute(viterbi_kernel, cudaFuncAttributeMaxDynamicSharedMemorySize, (int)vsm);
    viterbi_kernel<<<GB, 224, vsm>>>(trans, startt, stopt, out);
}